// round 2
// baseline (speedup 1.0000x reference)
#include <cuda_runtime.h>
#include <cstdint>

#define H 128
#define BM 128
#define SA 132                       // padded A-tile stride (floats), 16B-aligned rows
#define MAXN 50176
#define MAXE 800000

// -------- scratch (device globals; no allocations allowed) --------
__device__ float g_P[MAXN * H];      // x @ We1[0:128] + be1
__device__ float g_Q[MAXN * H];      // x @ We1[128:256]
__device__ float g_Hsum[MAXN * H];   // scatter-accumulated relu hidden
__device__ float g_agg[MAXN * H];    // Hsum @ We2 + deg*be2
__device__ float g_T[MAXN * H];      // relu(x@Wn1a + agg@Wn1b + bn1)
__device__ float g_deg[MAXN];
__device__ int   g_row[MAXE];
__device__ int   g_col[MAXE];
__device__ int   g_not64;            // nonzero => edge_index is int32

// -------- helpers --------
__device__ __forceinline__ void red_add_v4(float* p, float4 v) {
    asm volatile("red.global.add.v4.f32 [%0], {%1,%2,%3,%4};"
                 :: "l"(p), "f"(v.x), "f"(v.y), "f"(v.z), "f"(v.w) : "memory");
}

__device__ __forceinline__ void load_A_tile(const float* __restrict__ A, int gm, int M,
                                            float* __restrict__ As, int tid) {
#pragma unroll
    for (int it = 0; it < 16; ++it) {
        int idx = tid + it * 256;              // 0..4095
        int m = idx >> 5;
        int k4 = (idx & 31) << 2;
        float4 v = make_float4(0.f, 0.f, 0.f, 0.f);
        int gr = gm + m;
        if (gr < M) v = *(const float4*)(A + (size_t)gr * H + k4);
        *(float4*)(As + m * SA + k4) = v;
    }
}

__device__ __forceinline__ void load_W_tile(const float* __restrict__ W,
                                            float* __restrict__ Ws, int tid) {
#pragma unroll
    for (int it = 0; it < 16; ++it) {
        int idx = tid + it * 256;
        ((float4*)Ws)[idx] = ((const float4*)W)[idx];
    }
}

// 128x128x128 fp32 register-tiled MAC: 256 threads, 8 rows x (4+4) cols per thread
__device__ __forceinline__ void gemm_compute(const float* __restrict__ As,
                                             const float* __restrict__ Ws,
                                             float acc[8][8], int tx, int ty) {
#pragma unroll 2
    for (int k = 0; k < 128; k += 4) {
        float a[8][4];
#pragma unroll
        for (int i = 0; i < 8; ++i)
            *(float4*)a[i] = *(const float4*)(As + (ty * 8 + i) * SA + k);
#pragma unroll
        for (int kk = 0; kk < 4; ++kk) {
            float4 w0 = *(const float4*)(Ws + (k + kk) * 128 + tx * 4);
            float4 w1 = *(const float4*)(Ws + (k + kk) * 128 + tx * 4 + 64);
#pragma unroll
            for (int i = 0; i < 8; ++i) {
                float av = a[i][kk];
                acc[i][0] = fmaf(av, w0.x, acc[i][0]);
                acc[i][1] = fmaf(av, w0.y, acc[i][1]);
                acc[i][2] = fmaf(av, w0.z, acc[i][2]);
                acc[i][3] = fmaf(av, w0.w, acc[i][3]);
                acc[i][4] = fmaf(av, w1.x, acc[i][4]);
                acc[i][5] = fmaf(av, w1.y, acc[i][5]);
                acc[i][6] = fmaf(av, w1.z, acc[i][6]);
                acc[i][7] = fmaf(av, w1.w, acc[i][7]);
            }
        }
    }
}

// -------- index dtype sniffing + normalization --------
__global__ void detect_idx(const long long* __restrict__ ei, int E, int N) {
    // Reads only the first E int64 slots: safe for both dtypes (buffer >= E*8 bytes).
    // Genuine int64 row indices are all in [0,N). int32 data reinterpreted as
    // int64 fuses index pairs into huge values -> flag trips.
    int i = blockIdx.x * blockDim.x + threadIdx.x;
    int stride = gridDim.x * blockDim.x;
    int bad = 0;
    for (int e = i; e < E; e += stride) {
        long long v = ei[e];
        if (v < 0 || v >= (long long)N) bad = 1;
    }
    if (__syncthreads_or(bad) && threadIdx.x == 0) atomicOr(&g_not64, 1);
}

__global__ void convert_idx(const void* __restrict__ ei, int E, int N,
                            int* __restrict__ row, int* __restrict__ col) {
    int e = blockIdx.x * blockDim.x + threadIdx.x;
    if (e >= E) return;
    int r, c;
    if (g_not64) {
        const int* p = (const int*)ei;
        r = p[e]; c = p[E + e];
    } else {
        const long long* p = (const long long*)ei;
        r = (int)p[e]; c = (int)p[E + e];
    }
    row[e] = min(max(r, 0), N - 1);
    col[e] = min(max(c, 0), N - 1);
}

// -------- node-side GEMM: C = act(A1@W1 [+ A2@W2] + bias) --------
// BIAS_MODE: 0 = none, 1 = +bias[n], 2 = +deg[m]*bias[n]
template<bool DUAL, bool RELU, int BIAS_MODE>
__global__ void __launch_bounds__(256, 1)
node_gemm(const float* __restrict__ A1, const float* __restrict__ W1,
          const float* __restrict__ A2, const float* __restrict__ W2,
          const float* __restrict__ bias, const float* __restrict__ deg,
          float* __restrict__ C, int M) {
    extern __shared__ float sm[];
    float* As = sm;
    float* Ws = sm + BM * SA;
    int tid = threadIdx.x, tx = tid & 15, ty = tid >> 4;
    int gm = blockIdx.x * BM;

    float acc[8][8];
#pragma unroll
    for (int i = 0; i < 8; ++i)
#pragma unroll
        for (int j = 0; j < 8; ++j) acc[i][j] = 0.f;

    load_A_tile(A1, gm, M, As, tid);
    load_W_tile(W1, Ws, tid);
    __syncthreads();
    gemm_compute(As, Ws, acc, tx, ty);
    if (DUAL) {
        __syncthreads();
        load_A_tile(A2, gm, M, As, tid);
        load_W_tile(W2, Ws, tid);
        __syncthreads();
        gemm_compute(As, Ws, acc, tx, ty);
    }

    int c0 = tx * 4;
    float4 b0 = make_float4(0, 0, 0, 0), b1 = make_float4(0, 0, 0, 0);
    if (BIAS_MODE != 0) {
        b0 = *(const float4*)(bias + c0);
        b1 = *(const float4*)(bias + c0 + 64);
    }
#pragma unroll
    for (int i = 0; i < 8; ++i) {
        int m = gm + ty * 8 + i;
        if (m < M) {
            float4 v0 = make_float4(acc[i][0], acc[i][1], acc[i][2], acc[i][3]);
            float4 v1 = make_float4(acc[i][4], acc[i][5], acc[i][6], acc[i][7]);
            if (BIAS_MODE == 1) {
                v0.x += b0.x; v0.y += b0.y; v0.z += b0.z; v0.w += b0.w;
                v1.x += b1.x; v1.y += b1.y; v1.z += b1.z; v1.w += b1.w;
            } else if (BIAS_MODE == 2) {
                float d = deg[m];
                v0.x += d * b0.x; v0.y += d * b0.y; v0.z += d * b0.z; v0.w += d * b0.w;
                v1.x += d * b1.x; v1.y += d * b1.y; v1.z += d * b1.z; v1.w += d * b1.w;
            }
            if (RELU) {
                v0.x = fmaxf(v0.x, 0.f); v0.y = fmaxf(v0.y, 0.f);
                v0.z = fmaxf(v0.z, 0.f); v0.w = fmaxf(v0.w, 0.f);
                v1.x = fmaxf(v1.x, 0.f); v1.y = fmaxf(v1.y, 0.f);
                v1.z = fmaxf(v1.z, 0.f); v1.w = fmaxf(v1.w, 0.f);
            }
            *(float4*)(C + (size_t)m * H + c0) = v0;
            *(float4*)(C + (size_t)m * H + c0 + 64) = v1;
        }
    }
}

// -------- edge kernel: h = relu(EA@We1c + P[row] + Q[col]); Hsum[col] += h --------
__global__ void __launch_bounds__(256, 1)
edge_gemm(const float* __restrict__ EA, const float* __restrict__ Wc,
          const int* __restrict__ rowi, const int* __restrict__ coli,
          const float* __restrict__ P, const float* __restrict__ Q,
          float* __restrict__ Hsum, float* __restrict__ deg, int E) {
    extern __shared__ float sm[];
    float* As = sm;
    float* Ws = sm + BM * SA;
    int* ridx = (int*)(Ws + 128 * 128);
    int* cidx = ridx + 128;
    int tid = threadIdx.x, tx = tid & 15, ty = tid >> 4;
    int ge = blockIdx.x * BM;

    if (tid < 128) {
        int e = ge + tid;
        ridx[tid] = (e < E) ? rowi[e] : 0;
        cidx[tid] = (e < E) ? coli[e] : 0;
    }
    load_A_tile(EA, ge, E, As, tid);
    load_W_tile(Wc, Ws, tid);
    __syncthreads();

    float acc[8][8];
#pragma unroll
    for (int i = 0; i < 8; ++i)
#pragma unroll
        for (int j = 0; j < 8; ++j) acc[i][j] = 0.f;
    gemm_compute(As, Ws, acc, tx, ty);

    int c0 = tx * 4;
#pragma unroll
    for (int i = 0; i < 8; ++i) {
        int li = ty * 8 + i;
        int e = ge + li;
        if (e < E) {
            int r = ridx[li], c = cidx[li];
            float4 p0 = *(const float4*)(P + (size_t)r * H + c0);
            float4 p1 = *(const float4*)(P + (size_t)r * H + c0 + 64);
            float4 q0 = *(const float4*)(Q + (size_t)c * H + c0);
            float4 q1 = *(const float4*)(Q + (size_t)c * H + c0 + 64);
            float4 v0, v1;
            v0.x = fmaxf(acc[i][0] + p0.x + q0.x, 0.f);
            v0.y = fmaxf(acc[i][1] + p0.y + q0.y, 0.f);
            v0.z = fmaxf(acc[i][2] + p0.z + q0.z, 0.f);
            v0.w = fmaxf(acc[i][3] + p0.w + q0.w, 0.f);
            v1.x = fmaxf(acc[i][4] + p1.x + q1.x, 0.f);
            v1.y = fmaxf(acc[i][5] + p1.y + q1.y, 0.f);
            v1.z = fmaxf(acc[i][6] + p1.z + q1.z, 0.f);
            v1.w = fmaxf(acc[i][7] + p1.w + q1.w, 0.f);
            red_add_v4(Hsum + (size_t)c * H + c0, v0);
            red_add_v4(Hsum + (size_t)c * H + c0 + 64, v1);
        }
    }
    if (tx == 0) {
#pragma unroll
        for (int i = 0; i < 8; ++i) {
            int li = ty * 8 + i;
            if (ge + li < E) atomicAdd(&deg[cidx[li]], 1.0f);
        }
    }
}

__global__ void zero_kernel(float* __restrict__ hs, float* __restrict__ dg,
                            int nh, int nd) {
    int i = blockIdx.x * blockDim.x + threadIdx.x;
    if (i < nh) hs[i] = 0.f;
    if (i < nd) dg[i] = 0.f;
    if (i == 0) g_not64 = 0;
}

// -------- host --------
static const int SMEM_NODE = (BM * SA + 128 * 128) * 4;          // 133120 B
static const int SMEM_EDGE = SMEM_NODE + 2 * 128 * 4;            // 134144 B

extern "C" void kernel_launch(void* const* d_in, const int* in_sizes, int n_in,
                              void* d_out, int out_size) {
    const float* x    = (const float*)d_in[0];
    const void*  ei   = d_in[1];
    const float* ea   = (const float*)d_in[2];
    const float* We1  = (const float*)d_in[3];
    const float* be1  = (const float*)d_in[4];
    const float* We2  = (const float*)d_in[5];
    const float* be2  = (const float*)d_in[6];
    const float* Wn1  = (const float*)d_in[7];
    const float* bn1  = (const float*)d_in[8];
    const float* Wn2  = (const float*)d_in[9];
    const float* bn2  = (const float*)d_in[10];
    float* out = (float*)d_out;

    int N = in_sizes[0] / H;
    int E = in_sizes[1] / 2;

    void *pP, *pQ, *pHs, *pAgg, *pT, *pDeg, *pRow, *pCol;
    cudaGetSymbolAddress(&pP, g_P);
    cudaGetSymbolAddress(&pQ, g_Q);
    cudaGetSymbolAddress(&pHs, g_Hsum);
    cudaGetSymbolAddress(&pAgg, g_agg);
    cudaGetSymbolAddress(&pT, g_T);
    cudaGetSymbolAddress(&pDeg, g_deg);
    cudaGetSymbolAddress(&pRow, g_row);
    cudaGetSymbolAddress(&pCol, g_col);
    float* P   = (float*)pP;
    float* Q   = (float*)pQ;
    float* Hs  = (float*)pHs;
    float* agg = (float*)pAgg;
    float* T   = (float*)pT;
    float* dg  = (float*)pDeg;
    int*   ro  = (int*)pRow;
    int*   co  = (int*)pCol;

    cudaFuncSetAttribute(node_gemm<false, false, 0>, cudaFuncAttributeMaxDynamicSharedMemorySize, SMEM_NODE);
    cudaFuncSetAttribute(node_gemm<false, false, 1>, cudaFuncAttributeMaxDynamicSharedMemorySize, SMEM_NODE);
    cudaFuncSetAttribute(node_gemm<false, false, 2>, cudaFuncAttributeMaxDynamicSharedMemorySize, SMEM_NODE);
    cudaFuncSetAttribute(node_gemm<true,  true,  1>, cudaFuncAttributeMaxDynamicSharedMemorySize, SMEM_NODE);
    cudaFuncSetAttribute(edge_gemm, cudaFuncAttributeMaxDynamicSharedMemorySize, SMEM_EDGE);

    int nodeBlocks = (N + BM - 1) / BM;
    int edgeBlocks = (E + BM - 1) / BM;
    int nh = N * H;

    // 0) zero scatter buffers + dtype flag
    zero_kernel<<<(nh + 255) / 256, 256>>>(Hs, dg, nh, N);
    // 0b) sniff edge_index dtype, normalize to int32 scratch
    detect_idx<<<512, 256>>>((const long long*)ei, E, N);
    convert_idx<<<(E + 255) / 256, 256>>>(ei, E, N, ro, co);
    // 1) P = x @ We1[0:128] + be1 ; Q = x @ We1[128:256]
    node_gemm<false, false, 1><<<nodeBlocks, 256, SMEM_NODE>>>(x, We1, nullptr, nullptr, be1, nullptr, P, N);
    node_gemm<false, false, 0><<<nodeBlocks, 256, SMEM_NODE>>>(x, We1 + 128 * 128, nullptr, nullptr, nullptr, nullptr, Q, N);
    // 2) edge: h = relu(EA@We1c + P[row] + Q[col]); Hsum[col] += h; deg[col]++
    edge_gemm<<<edgeBlocks, 256, SMEM_EDGE>>>(ea, We1 + 256 * 128, ro, co, P, Q, Hs, dg, E);
    // 3) agg = Hsum @ We2 + deg*be2
    node_gemm<false, false, 2><<<nodeBlocks, 256, SMEM_NODE>>>(Hs, We2, nullptr, nullptr, be2, dg, agg, N);
    // 4) T = relu(x@Wn1[0:128] + agg@Wn1[128:256] + bn1)
    node_gemm<true, true, 1><<<nodeBlocks, 256, SMEM_NODE>>>(x, Wn1, agg, Wn1 + 128 * 128, bn1, nullptr, T, N);
    // 5) out = T @ Wn2 + bn2
    node_gemm<false, false, 1><<<nodeBlocks, 256, SMEM_NODE>>>(T, Wn2, nullptr, nullptr, bn2, nullptr, out, N);
}

// round 6
// speedup vs baseline: 1.1374x; 1.1374x over previous
#include <cuda_runtime.h>
#include <cuda_bf16.h>
#include <cstdint>

#define H 128
#define BM 128
#define MAXN 50176
#define MAXE 800000

// ---------------- scratch (device globals) ----------------
__device__ float g_P[MAXN * H];
__device__ float g_Q[MAXN * H];
__device__ float g_Hsum[MAXN * H];
__device__ float g_agg[MAXN * H];
__device__ float g_Tbuf[MAXN * H];
__device__ float g_deg[MAXN];
__device__ int   g_row[MAXE];
__device__ int   g_col[MAXE];
__device__ int   g_not64;
// 7 weight tiles x (hi,lo): B^T[n][k] bf16, packed 256B rows, 32KB each
__device__ __align__(16) char g_Wimg[14 * 32768];

// ---------------- smem layout ----------------
// bf16 tiles with 272B row stride (136 bf16): 16B-aligned rows, ldmatrix
// conflict-free (272 mod 128 = 16 -> 8 consecutive rows hit 8 distinct 16B lanes)
#define TSTRIDE 272
#define TILE    (128 * TSTRIDE)      // 34816
#define SM_AH   0
#define SM_AL   TILE
#define SM_WH   (2 * TILE)
#define SM_WL   (3 * TILE)
#define SM_RIDX (4 * TILE)
#define SM_CIDX (4 * TILE + 512)
#define SMEM_NODE (4 * TILE)
#define SMEM_EDGE (4 * TILE + 1024)

// ---------------- PTX helpers ----------------
__device__ __forceinline__ uint32_t smem_u32(const void* p) {
    uint32_t a;
    asm("{ .reg .u64 t; cvta.to.shared.u64 t, %1; cvt.u32.u64 %0, t; }" : "=r"(a) : "l"(p));
    return a;
}
__device__ __forceinline__ void ldsm_x4(uint32_t* r, uint32_t addr) {
    asm volatile("ldmatrix.sync.aligned.m8n8.x4.shared.b16 {%0,%1,%2,%3}, [%4];"
                 : "=r"(r[0]), "=r"(r[1]), "=r"(r[2]), "=r"(r[3]) : "r"(addr));
}
__device__ __forceinline__ void mma16816(float* d, const uint32_t* a, uint32_t b0, uint32_t b1) {
    asm volatile("mma.sync.aligned.m16n8k16.row.col.f32.bf16.bf16.f32 "
                 "{%0,%1,%2,%3}, {%4,%5,%6,%7}, {%8,%9}, {%0,%1,%2,%3};"
                 : "+f"(d[0]), "+f"(d[1]), "+f"(d[2]), "+f"(d[3])
                 : "r"(a[0]), "r"(a[1]), "r"(a[2]), "r"(a[3]), "r"(b0), "r"(b1));
}
__device__ __forceinline__ void red_add_v2(float* p, float a, float b) {
    asm volatile("red.global.add.v2.f32 [%0], {%1,%2};" :: "l"(p), "f"(a), "f"(b) : "memory");
}

__device__ __forceinline__ void split2(float a, float b, uint32_t& hi, uint32_t& lo) {
    __nv_bfloat16 ha = __float2bfloat16_rn(a), hb = __float2bfloat16_rn(b);
    float ra = a - __bfloat162float(ha), rb = b - __bfloat162float(hb);
    __nv_bfloat16 la = __float2bfloat16_rn(ra), lb = __float2bfloat16_rn(rb);
    hi = ((uint32_t)*(uint16_t*)&hb << 16) | (uint32_t)*(uint16_t*)&ha;
    lo = ((uint32_t)*(uint16_t*)&lb << 16) | (uint32_t)*(uint16_t*)&la;
}

// load fp32 A tile, split to bf16 hi/lo smem tiles (row stride 272B)
__device__ __forceinline__ void load_convert_A(const float* __restrict__ A, int gm, int M,
                                               char* sm, int tid) {
#pragma unroll
    for (int it = 0; it < 16; ++it) {
        int idx = tid + it * 256;              // 0..4095
        int m = idx >> 5;
        int k4 = (idx & 31) << 2;
        float4 v = make_float4(0.f, 0.f, 0.f, 0.f);
        int gr = gm + m;
        if (gr < M) v = *(const float4*)(A + (size_t)gr * H + k4);
        uint32_t h0, l0, h1, l1;
        split2(v.x, v.y, h0, l0);
        split2(v.z, v.w, h1, l1);
        uint32_t off = (uint32_t)m * TSTRIDE + (uint32_t)k4 * 2;
        *(uint2*)(sm + SM_AH + off) = make_uint2(h0, h1);
        *(uint2*)(sm + SM_AL + off) = make_uint2(l0, l1);
    }
}

// copy packed 32KB weight images (hi,lo) into strided smem tiles
__device__ __forceinline__ void copy_W(const char* __restrict__ wh, const char* __restrict__ wl,
                                       char* sm, int tid) {
#pragma unroll
    for (int it = 0; it < 8; ++it) {
        int idx = tid + it * 256;              // 0..2047 uint4 chunks
        int row = idx >> 4;
        int chunk = idx & 15;
        uint32_t off = (uint32_t)row * TSTRIDE + (uint32_t)chunk * 16;
        *(uint4*)(sm + SM_WH + off) = ((const uint4*)wh)[idx];
        *(uint4*)(sm + SM_WL + off) = ((const uint4*)wl)[idx];
    }
}

// 3-term compensated HMMA: acc += Ah*Wh + Ah*Wl + Al*Wh
// warp tile: 64x32 (wm in {0,1}, wn in {0..3}); acc[mf][nf][4]
__device__ __forceinline__ void gemm_hmma(uint32_t sb, int wm, int wn, int lane,
                                          float acc[4][4][4]) {
    uint32_t aRowBase = (uint32_t)(wm * 64 + (lane & 15)) * TSTRIDE + (uint32_t)(lane >> 4) * 16;
    uint32_t bRowBase = (uint32_t)(wn * 32 + (lane & 15)) * TSTRIDE + (uint32_t)(lane >> 4) * 16;
#pragma unroll
    for (int t = 0; t < 3; ++t) {
        uint32_t aBase = sb + (t == 2 ? SM_AL : SM_AH) + aRowBase;
        uint32_t wBase = sb + (t == 1 ? SM_WL : SM_WH) + bRowBase;
#pragma unroll
        for (int kf = 0; kf < 8; ++kf) {
            uint32_t af[4][4], bf[2][4];
#pragma unroll
            for (int mf = 0; mf < 4; ++mf)
                ldsm_x4(af[mf], aBase + mf * 16 * TSTRIDE + kf * 32);
#pragma unroll
            for (int p = 0; p < 2; ++p)
                ldsm_x4(bf[p], wBase + p * 16 * TSTRIDE + kf * 32);
#pragma unroll
            for (int mf = 0; mf < 4; ++mf) {
                mma16816(acc[mf][0], af[mf], bf[0][0], bf[0][2]);
                mma16816(acc[mf][1], af[mf], bf[0][1], bf[0][3]);
                mma16816(acc[mf][2], af[mf], bf[1][0], bf[1][2]);
                mma16816(acc[mf][3], af[mf], bf[1][1], bf[1][3]);
            }
        }
    }
}

// ---------------- index sniffing ----------------
__global__ void detect_idx(const long long* __restrict__ ei, int E, int N) {
    int i = blockIdx.x * blockDim.x + threadIdx.x;
    int stride = gridDim.x * blockDim.x;
    int bad = 0;
    for (int e = i; e < E; e += stride) {
        long long v = ei[e];
        if (v < 0 || v >= (long long)N) bad = 1;
    }
    if (__syncthreads_or(bad) && threadIdx.x == 0) atomicOr(&g_not64, 1);
}

__global__ void convert_idx(const void* __restrict__ ei, int E, int N,
                            int* __restrict__ row, int* __restrict__ col,
                            float* __restrict__ deg) {
    int e = blockIdx.x * blockDim.x + threadIdx.x;
    if (e >= E) return;
    int r, c;
    if (g_not64) {
        const int* p = (const int*)ei;
        r = p[e]; c = p[E + e];
    } else {
        const long long* p = (const long long*)ei;
        r = (int)p[e]; c = (int)p[E + e];
    }
    r = min(max(r, 0), N - 1);
    c = min(max(c, 0), N - 1);
    row[e] = r;
    col[e] = c;
    atomicAdd(&deg[c], 1.0f);
}

// ---------------- weight preconvert: W[k][n] -> B^T[n][k] hi/lo packed bf16 ----------------
__global__ void prep_weights(const float* __restrict__ We1, const float* __restrict__ We2,
                             const float* __restrict__ Wn1, const float* __restrict__ Wn2) {
    int task = blockIdx.x * blockDim.x + threadIdx.x;   // 7*4096
    if (task >= 7 * 4096) return;
    int t = task >> 12;
    int r = task & 4095;
    int n = r >> 5;
    int k4 = (r & 31) << 2;
    const float* src;
    switch (t) {
        case 0: src = We1;          break;
        case 1: src = We1 + 16384;  break;
        case 2: src = We1 + 32768;  break;
        case 3: src = We2;          break;
        case 4: src = Wn1;          break;
        case 5: src = Wn1 + 16384;  break;
        default: src = Wn2;         break;
    }
    float v0 = src[(k4 + 0) * H + n];
    float v1 = src[(k4 + 1) * H + n];
    float v2 = src[(k4 + 2) * H + n];
    float v3 = src[(k4 + 3) * H + n];
    uint32_t h0, l0, h1, l1;
    split2(v0, v1, h0, l0);
    split2(v2, v3, h1, l1);
    uint32_t off = (uint32_t)n * 256 + (uint32_t)k4 * 2;
    *(uint2*)(g_Wimg + (size_t)t * 32768 + off)       = make_uint2(h0, h1);
    *(uint2*)(g_Wimg + (size_t)(7 + t) * 32768 + off) = make_uint2(l0, l1);
}

// ---------------- node GEMM: C = act(A1@W1 [+ A2@W2] + bias) ----------------
template<bool DUAL, bool RELU, int BIAS_MODE>
__global__ void __launch_bounds__(256, 1)
node_gemm(const float* __restrict__ A1, const char* __restrict__ w1h, const char* __restrict__ w1l,
          const float* __restrict__ A2, const char* __restrict__ w2h, const char* __restrict__ w2l,
          const float* __restrict__ bias, const float* __restrict__ deg,
          float* __restrict__ C, int M) {
    extern __shared__ char sm[];
    uint32_t sb = smem_u32(sm);
    int tid = threadIdx.x, lane = tid & 31, wid = tid >> 5;
    int wm = wid & 1, wn = wid >> 1;
    int gm = blockIdx.x * BM;

    float acc[4][4][4];
#pragma unroll
    for (int a = 0; a < 4; ++a)
#pragma unroll
        for (int b = 0; b < 4; ++b)
#pragma unroll
            for (int c = 0; c < 4; ++c) acc[a][b][c] = 0.f;

    load_convert_A(A1, gm, M, sm, tid);
    copy_W(w1h, w1l, sm, tid);
    __syncthreads();
    gemm_hmma(sb, wm, wn, lane, acc);
    if (DUAL) {
        __syncthreads();
        load_convert_A(A2, gm, M, sm, tid);
        copy_W(w2h, w2l, sm, tid);
        __syncthreads();
        gemm_hmma(sb, wm, wn, lane, acc);
    }

#pragma unroll
    for (int mf = 0; mf < 4; ++mf) {
        int r0 = gm + wm * 64 + mf * 16 + (lane >> 2);
        int r1 = r0 + 8;
        float d0 = 0.f, d1 = 0.f;
        if (BIAS_MODE == 2) {
            if (r0 < M) d0 = deg[r0];
            if (r1 < M) d1 = deg[r1];
        }
#pragma unroll
        for (int nf = 0; nf < 4; ++nf) {
            int c = wn * 32 + nf * 8 + (lane & 3) * 2;
            float bx = 0.f, by = 0.f;
            if (BIAS_MODE != 0) {
                float2 b = *(const float2*)(bias + c);
                bx = b.x; by = b.y;
            }
            if (r0 < M) {
                float vx = acc[mf][nf][0], vy = acc[mf][nf][1];
                if (BIAS_MODE == 1) { vx += bx; vy += by; }
                else if (BIAS_MODE == 2) { vx += d0 * bx; vy += d0 * by; }
                if (RELU) { vx = fmaxf(vx, 0.f); vy = fmaxf(vy, 0.f); }
                *(float2*)(C + (size_t)r0 * H + c) = make_float2(vx, vy);
            }
            if (r1 < M) {
                float vx = acc[mf][nf][2], vy = acc[mf][nf][3];
                if (BIAS_MODE == 1) { vx += bx; vy += by; }
                else if (BIAS_MODE == 2) { vx += d1 * bx; vy += d1 * by; }
                if (RELU) { vx = fmaxf(vx, 0.f); vy = fmaxf(vy, 0.f); }
                *(float2*)(C + (size_t)r1 * H + c) = make_float2(vx, vy);
            }
        }
    }
}

// ---------------- edge GEMM: h = relu(EA@We1c + P[row] + Q[col]); Hsum[col] += h ----------------
__global__ void __launch_bounds__(256, 1)
edge_gemm(const float* __restrict__ EA, const char* __restrict__ wh, const char* __restrict__ wl,
          const int* __restrict__ rowi, const int* __restrict__ coli,
          const float* __restrict__ P, const float* __restrict__ Q,
          float* __restrict__ Hsum, int E) {
    extern __shared__ char sm[];
    uint32_t sb = smem_u32(sm);
    int tid = threadIdx.x, lane = tid & 31, wid = tid >> 5;
    int wm = wid & 1, wn = wid >> 1;
    int ge = blockIdx.x * BM;

    if (tid < 128) {
        int e = ge + tid;
        ((int*)(sm + SM_RIDX))[tid] = (e < E) ? rowi[e] : 0;
        ((int*)(sm + SM_CIDX))[tid] = (e < E) ? coli[e] : 0;
    }
    load_convert_A(EA, ge, E, sm, tid);
    copy_W(wh, wl, sm, tid);
    __syncthreads();

    float acc[4][4][4];
#pragma unroll
    for (int a = 0; a < 4; ++a)
#pragma unroll
        for (int b = 0; b < 4; ++b)
#pragma unroll
            for (int c = 0; c < 4; ++c) acc[a][b][c] = 0.f;
    gemm_hmma(sb, wm, wn, lane, acc);

    const int* ridx = (const int*)(sm + SM_RIDX);
    const int* cidx = (const int*)(sm + SM_CIDX);
#pragma unroll
    for (int mf = 0; mf < 4; ++mf) {
        int li0 = wm * 64 + mf * 16 + (lane >> 2);
        int li1 = li0 + 8;
        int e0 = ge + li0, e1 = ge + li1;
        int r0 = ridx[li0], c0 = cidx[li0];
        int r1 = ridx[li1], c1 = cidx[li1];
#pragma unroll
        for (int nf = 0; nf < 4; ++nf) {
            int c = wn * 32 + nf * 8 + (lane & 3) * 2;
            if (e0 < E) {
                float2 pv = *(const float2*)(P + (size_t)r0 * H + c);
                float2 qv = *(const float2*)(Q + (size_t)c0 * H + c);
                float vx = fmaxf(acc[mf][nf][0] + pv.x + qv.x, 0.f);
                float vy = fmaxf(acc[mf][nf][1] + pv.y + qv.y, 0.f);
                red_add_v2(Hsum + (size_t)c0 * H + c, vx, vy);
            }
            if (e1 < E) {
                float2 pv = *(const float2*)(P + (size_t)r1 * H + c);
                float2 qv = *(const float2*)(Q + (size_t)c1 * H + c);
                float vx = fmaxf(acc[mf][nf][2] + pv.x + qv.x, 0.f);
                float vy = fmaxf(acc[mf][nf][3] + pv.y + qv.y, 0.f);
                red_add_v2(Hsum + (size_t)c1 * H + c, vx, vy);
            }
        }
    }
}

__global__ void zero_kernel(float* __restrict__ hs, float* __restrict__ dg, int nh, int nd) {
    int i = blockIdx.x * blockDim.x + threadIdx.x;
    if (i < nh) hs[i] = 0.f;
    if (i < nd) dg[i] = 0.f;
    if (i == 0) g_not64 = 0;
}

// ---------------- host ----------------
extern "C" void kernel_launch(void* const* d_in, const int* in_sizes, int n_in,
                              void* d_out, int out_size) {
    const float* x   = (const float*)d_in[0];
    const void*  ei  = d_in[1];
    const float* ea  = (const float*)d_in[2];
    const float* We1 = (const float*)d_in[3];
    const float* be1 = (const float*)d_in[4];
    const float* We2 = (const float*)d_in[5];
    const float* be2 = (const float*)d_in[6];
    const float* Wn1 = (const float*)d_in[7];
    const float* bn1 = (const float*)d_in[8];
    const float* Wn2 = (const float*)d_in[9];
    const float* bn2 = (const float*)d_in[10];
    float* out = (float*)d_out;

    int N = in_sizes[0] / H;
    int E = in_sizes[1] / 2;

    void *pP, *pQ, *pHs, *pAgg, *pT, *pDeg, *pRow, *pCol, *pWimg;
    cudaGetSymbolAddress(&pP, g_P);
    cudaGetSymbolAddress(&pQ, g_Q);
    cudaGetSymbolAddress(&pHs, g_Hsum);
    cudaGetSymbolAddress(&pAgg, g_agg);
    cudaGetSymbolAddress(&pT, g_Tbuf);
    cudaGetSymbolAddress(&pDeg, g_deg);
    cudaGetSymbolAddress(&pRow, g_row);
    cudaGetSymbolAddress(&pCol, g_col);
    cudaGetSymbolAddress(&pWimg, g_Wimg);
    float* P   = (float*)pP;
    float* Q   = (float*)pQ;
    float* Hs  = (float*)pHs;
    float* agg = (float*)pAgg;
    float* T   = (float*)pT;
    float* dg  = (float*)pDeg;
    int*   ro  = (int*)pRow;
    int*   co  = (int*)pCol;
    const char* W = (const char*)pWimg;
    auto wH = [&](int t) { return W + (size_t)t * 32768; };
    auto wL = [&](int t) { return W + (size_t)(7 + t) * 32768; };

    cudaFuncSetAttribute(node_gemm<false, false, 0>, cudaFuncAttributeMaxDynamicSharedMemorySize, SMEM_NODE);
    cudaFuncSetAttribute(node_gemm<false, false, 1>, cudaFuncAttributeMaxDynamicSharedMemorySize, SMEM_NODE);
    cudaFuncSetAttribute(node_gemm<false, false, 2>, cudaFuncAttributeMaxDynamicSharedMemorySize, SMEM_NODE);
    cudaFuncSetAttribute(node_gemm<true,  true,  1>, cudaFuncAttributeMaxDynamicSharedMemorySize, SMEM_NODE);
    cudaFuncSetAttribute(edge_gemm, cudaFuncAttributeMaxDynamicSharedMemorySize, SMEM_EDGE);

    int nodeBlocks = (N + BM - 1) / BM;
    int edgeBlocks = (E + BM - 1) / BM;
    int nh = N * H;

    // 0) zero scatter buffers + dtype flag
    zero_kernel<<<(nh + 255) / 256, 256>>>(Hs, dg, nh, N);
    // 0b) sniff index dtype, normalize + degree count
    detect_idx<<<512, 256>>>((const long long*)ei, E, N);
    convert_idx<<<(E + 255) / 256, 256>>>(ei, E, N, ro, co, dg);
    // 0c) weights -> transposed + hi/lo split bf16 images
    prep_weights<<<112, 256>>>(We1, We2, Wn1, Wn2);
    // 1) P = x@We1a + be1 ; Q = x@We1b
    node_gemm<false, false, 1><<<nodeBlocks, 256, SMEM_NODE>>>(x, wH(0), wL(0), nullptr, nullptr, nullptr, be1, nullptr, P, N);
    node_gemm<false, false, 0><<<nodeBlocks, 256, SMEM_NODE>>>(x, wH(1), wL(1), nullptr, nullptr, nullptr, nullptr, nullptr, Q, N);
    // 2) edge: h = relu(EA@We1c + P[row] + Q[col]); Hsum[col] += h
    edge_gemm<<<edgeBlocks, 256, SMEM_EDGE>>>(ea, wH(2), wL(2), ro, co, P, Q, Hs, E);
    // 3) agg = Hsum@We2 + deg*be2
    node_gemm<false, false, 2><<<nodeBlocks, 256, SMEM_NODE>>>(Hs, wH(3), wL(3), nullptr, nullptr, nullptr, be2, dg, agg, N);
    // 4) T = relu(x@Wn1a + agg@Wn1b + bn1)
    node_gemm<true, true, 1><<<nodeBlocks, 256, SMEM_NODE>>>(x, wH(4), wL(4), agg, wH(5), wL(5), bn1, nullptr, T, N);
    // 5) out = T@Wn2 + bn2
    node_gemm<false, false, 1><<<nodeBlocks, 256, SMEM_NODE>>>(T, wH(6), wL(6), nullptr, nullptr, nullptr, bn2, nullptr, out, N);
}